// round 2
// baseline (speedup 1.0000x reference)
#include <cuda_runtime.h>
#include <math.h>

#define SQ       2048
#define NH       16
#define DQK      576
#define KVL      512
#define NTOP     1024
#define SCALINGF 0.08838834764831845f  // 128^-0.5

// ------------------ device scratch (no allocation) ------------------
__device__ float g_ql  [SQ * 2048];        // q_latent @ wq_b^T
__device__ float g_ckv [SQ * 128];         // hs @ wk^T
__device__ float g_wtmp[SQ * NH];          // hs @ wproj^T
__device__ float g_iq  [SQ * NH * 128];    // index_q [s][h][128]
__device__ float g_ik  [SQ * 128];         // index_k [s][128]
__device__ float g_w   [SQ * NH];          // |wproj + b|
__device__ float g_q   [SQ * NH * DQK];    // q [s][h][576]
__device__ float g_kv  [SQ * DQK];         // kv [s][576]
__device__ float g_score[SQ * SQ];         // indexer scores (rows >=1024)
__device__ int   g_topk [SQ * NTOP];       // selected key indices (rows >=1024)
__device__ float g_attn [SQ * NH * KVL];   // softmax @ kv[:, :512]

// ------------------ generic batched SGEMM: C = A @ B(^T) ------------------
__global__ __launch_bounds__(256) void sgemm_k(
    const float* __restrict__ A, const float* __restrict__ B, float* __restrict__ C,
    int M, int N, int K, int lda, int ldb, int ldc,
    long long sA, long long sB, long long sC, int transB)
{
    A += (long long)blockIdx.z * sA;
    B += (long long)blockIdx.z * sB;
    C += (long long)blockIdx.z * sC;
    __shared__ float As[16][65];
    __shared__ float Bs[16][65];
    int tid = threadIdx.x, tx = tid & 15, ty = tid >> 4;
    int m0 = blockIdx.y * 64, n0 = blockIdx.x * 64;
    float acc[4][4] = {};
    for (int k0 = 0; k0 < K; k0 += 16) {
        for (int e = tid; e < 1024; e += 256) {
            int m = e >> 4, k = e & 15;
            int gm = m0 + m, gk = k0 + k;
            As[k][m] = (gm < M && gk < K) ? A[(long long)gm * lda + gk] : 0.f;
        }
        if (transB) {
            for (int e = tid; e < 1024; e += 256) {
                int n = e >> 4, k = e & 15;
                int gn = n0 + n, gk = k0 + k;
                Bs[k][n] = (gn < N && gk < K) ? B[(long long)gn * ldb + gk] : 0.f;
            }
        } else {
            for (int e = tid; e < 1024; e += 256) {
                int k = e >> 6, n = e & 63;
                int gn = n0 + n, gk = k0 + k;
                Bs[k][n] = (gn < N && gk < K) ? B[(long long)gk * ldb + gn] : 0.f;
            }
        }
        __syncthreads();
        #pragma unroll
        for (int kk = 0; kk < 16; kk++) {
            float a[4], b[4];
            #pragma unroll
            for (int i = 0; i < 4; i++) a[i] = As[kk][ty * 4 + i];
            #pragma unroll
            for (int j = 0; j < 4; j++) b[j] = Bs[kk][tx * 4 + j];
            #pragma unroll
            for (int i = 0; i < 4; i++)
                #pragma unroll
                for (int j = 0; j < 4; j++) acc[i][j] += a[i] * b[j];
        }
        __syncthreads();
    }
    #pragma unroll
    for (int i = 0; i < 4; i++) {
        int gm = m0 + ty * 4 + i;
        if (gm >= M) continue;
        #pragma unroll
        for (int j = 0; j < 4; j++) {
            int gn = n0 + tx * 4 + j;
            if (gn >= N) continue;
            C[(long long)gm * ldc + gn] = acc[i][j];
        }
    }
}

// ------------------ prep: rope / rmsnorm / concats ------------------
__global__ __launch_bounds__(128) void prep_k(
    const float* __restrict__ cosb, const float* __restrict__ sinb,
    const float* __restrict__ k_pass, const float* __restrict__ k_rot,
    const float* __restrict__ q_rot, const float* __restrict__ k_norm_w,
    const float* __restrict__ wproj_b)
{
    int s = blockIdx.x, t = threadIdx.x;
    const float* cs = cosb + s * 64;
    const float* sn = sinb + s * 64;
    // index_k rope (interleaved)
    if (t < 32) {
        float x0 = g_ckv[s * 128 + 2 * t], x1 = g_ckv[s * 128 + 2 * t + 1];
        g_ik[s * 128 + t]      = x0 * cs[t]      - x1 * sn[t];
        g_ik[s * 128 + 32 + t] = x1 * cs[32 + t] + x0 * sn[32 + t];
    }
    // rmsnorm of ckv[s][64:128]
    __shared__ float partials[4];
    float v = 0.f;
    if (t < 64) { float x = g_ckv[s * 128 + 64 + t]; v = x * x; }
    for (int o = 16; o > 0; o >>= 1) v += __shfl_xor_sync(0xffffffffu, v, o);
    if ((t & 31) == 0) partials[t >> 5] = v;
    __syncthreads();
    float var = (partials[0] + partials[1]) * (1.f / 64.f);
    float inv = rsqrtf(var + 1e-6f);
    if (t < 64)
        g_ik[s * 128 + 64 + t] = g_ckv[s * 128 + 64 + t] * inv * k_norm_w[t];
    // index_q: rope first 64 dims of each head, copy rest
    for (int u = t; u < 16 * 32; u += 128) {
        int h = u >> 5, i = u & 31;
        float x0 = g_ql[s * 2048 + h * 128 + 2 * i];
        float x1 = g_ql[s * 2048 + h * 128 + 2 * i + 1];
        g_iq[(s * 16 + h) * 128 + i]      = x0 * cs[i]      - x1 * sn[i];
        g_iq[(s * 16 + h) * 128 + 32 + i] = x1 * cs[32 + i] + x0 * sn[32 + i];
    }
    for (int u = t; u < 16 * 64; u += 128) {
        int h = u >> 6, i = u & 63;
        g_iq[(s * 16 + h) * 128 + 64 + i] = g_ql[s * 2048 + h * 128 + 64 + i];
    }
    // indexer weights
    if (t < 16) g_w[s * 16 + t] = fabsf(g_wtmp[s * 16 + t] + wproj_b[t]);
    // kv concat
    for (int u = t; u < 512; u += 128) g_kv[s * 576 + u] = k_pass[s * 512 + u];
    if (t < 64) g_kv[s * 576 + 512 + t] = k_rot[s * 64 + t];
    // q rope part (q_abs part written by sgemm)
    for (int u = t; u < 16 * 64; u += 128) {
        int h = u >> 6, j = u & 63;
        g_q[(s * 16 + h) * 576 + 512 + j] = q_rot[(h * 2048 + s) * 64 + j];
    }
}

// ------------------ indexer scores for rows q >= 1024 ------------------
__global__ __launch_bounds__(256) void score_k()
{
    __shared__ float Qs[32][65];
    __shared__ float Ks[32][65];
    __shared__ float ws[64];
    int q0 = 1024 + blockIdx.y * 64;
    int k0 = blockIdx.x * 64;
    if (k0 > q0 + 63) return;  // fully above diagonal
    int tid = threadIdx.x, tx = tid & 15, ty = tid >> 4;
    float acc[4][4] = {};
    for (int h = 0; h < 16; h++) {
        float dacc[4][4] = {};
        for (int d0 = 0; d0 < 128; d0 += 32) {
            __syncthreads();
            for (int e = tid; e < 2048; e += 256) {
                int m = e >> 5, dd = e & 31;
                Qs[dd][m] = g_iq[((q0 + m) * 16 + h) * 128 + d0 + dd];
                Ks[dd][m] = g_ik[(k0 + m) * 128 + d0 + dd];
            }
            __syncthreads();
            #pragma unroll
            for (int dd = 0; dd < 32; dd++) {
                float a[4], b[4];
                #pragma unroll
                for (int i = 0; i < 4; i++) a[i] = Qs[dd][ty * 4 + i];
                #pragma unroll
                for (int j = 0; j < 4; j++) b[j] = Ks[dd][tx * 4 + j];
                #pragma unroll
                for (int i = 0; i < 4; i++)
                    #pragma unroll
                    for (int j = 0; j < 4; j++) dacc[i][j] += a[i] * b[j];
            }
        }
        __syncthreads();
        if (tid < 64) ws[tid] = g_w[(q0 + tid) * 16 + h];
        __syncthreads();
        #pragma unroll
        for (int i = 0; i < 4; i++)
            #pragma unroll
            for (int j = 0; j < 4; j++)
                acc[i][j] += ws[ty * 4 + i] * fmaxf(dacc[i][j] * SCALINGF, 0.f);
    }
    #pragma unroll
    for (int i = 0; i < 4; i++)
        #pragma unroll
        for (int j = 0; j < 4; j++)
            g_score[(q0 + ty * 4 + i) * 2048 + k0 + tx * 4 + j] = acc[i][j];
}

// ------------------ top-1024 per row (bitonic, jax tie-break) ------------------
__global__ __launch_bounds__(1024) void topk_k()
{
    __shared__ unsigned long long key[2048];
    int q = 1024 + blockIdx.x;
    int t = threadIdx.x;
    for (int u = t; u < 2048; u += 1024) {
        unsigned long long kk = 0ull;
        if (u <= q) {
            unsigned int b = __float_as_uint(g_score[q * 2048 + u]);  // score >= 0
            kk = ((unsigned long long)b << 32) | (unsigned int)(~u);
        }
        key[u] = kk;
    }
    __syncthreads();
    for (int ks = 2; ks <= 2048; ks <<= 1) {
        for (int j = ks >> 1; j > 0; j >>= 1) {
            int i = ((t & ~(j - 1)) << 1) | (t & (j - 1));
            int p = i | j;
            bool desc = (i & ks) == 0;
            unsigned long long a = key[i], b = key[p];
            if ((a < b) == desc) { key[i] = b; key[p] = a; }
            __syncthreads();
        }
    }
    g_topk[q * 1024 + t] = (int)(~(unsigned int)(key[t] & 0xFFFFFFFFull));
}

// ------------------ gathered sparse attention (one row per block) ------------------
#define APITCH 577
#define LPITCH 1025
#define ATTN_SMEM ((16 * APITCH * 2 + 16 * LPITCH + 8 * 256) * 4)

__global__ __launch_bounds__(256) void attn_k()
{
    extern __shared__ float sm[];
    float* qs   = sm;                      // [16][577]
    float* kvs  = qs + 16 * APITCH;        // [16][577]
    float* lg   = kvs + 16 * APITCH;       // [16][1025]
    float* part = lg + 16 * LPITCH;        // [8][256]
    int q = blockIdx.x, t = threadIdx.x;
    int L = (q < 1024) ? (q + 1) : 1024;
    const int* sel = (q < 1024) ? (const int*)0 : &g_topk[q * 1024];

    for (int h = 0; h < 16; h++)
        for (int d = t; d < 576; d += 256)
            qs[h * APITCH + d] = g_q[(q * 16 + h) * 576 + d];

    int nt = (L + 15) >> 4;
    int wid = t >> 5, lane = t & 31;
    int lh = lane >> 3, lk = lane & 7;
    int d0 = wid * 72;

    // ---- pass 1: logits ----
    for (int tile = 0; tile < nt; tile++) {
        int j0 = tile << 4;
        __syncthreads();
        for (int j = 0; j < 16; j++) {
            int jj = j0 + j;
            if (jj < L) {
                int keyi = sel ? sel[jj] : jj;
                const float* src = &g_kv[keyi * 576];
                for (int d = t; d < 576; d += 256) kvs[j * APITCH + d] = src[d];
            } else {
                for (int d = t; d < 576; d += 256) kvs[j * APITCH + d] = 0.f;
            }
        }
        __syncthreads();
        float pa[4][2] = {};
        #pragma unroll 8
        for (int dd = 0; dd < 72; dd++) {
            int d = d0 + dd;
            float b0 = kvs[(lk * 2 + 0) * APITCH + d];
            float b1 = kvs[(lk * 2 + 1) * APITCH + d];
            #pragma unroll
            for (int i = 0; i < 4; i++) {
                float a = qs[(lh * 4 + i) * APITCH + d];
                pa[i][0] += a * b0;
                pa[i][1] += a * b1;
            }
        }
        #pragma unroll
        for (int i = 0; i < 4; i++)
            #pragma unroll
            for (int jj = 0; jj < 2; jj++)
                part[wid * 256 + (lh * 4 + i) * 16 + lk * 2 + jj] = pa[i][jj];
        __syncthreads();
        float ssum = 0.f;
        #pragma unroll
        for (int g2 = 0; g2 < 8; g2++) ssum += part[g2 * 256 + t];
        int hh = t >> 4, kk2 = t & 15;
        lg[hh * LPITCH + j0 + kk2] = (j0 + kk2 < L) ? ssum * SCALINGF : -1e30f;
    }
    __syncthreads();

    // ---- softmax over selected keys ----
    {
        int hh = t >> 4, sub = t & 15;
        int NT = nt << 4;
        float mx = -1e30f;
        for (int j = sub; j < NT; j += 16) mx = fmaxf(mx, lg[hh * LPITCH + j]);
        for (int o = 8; o; o >>= 1) mx = fmaxf(mx, __shfl_xor_sync(0xffffffffu, mx, o));
        float sme = 0.f;
        for (int j = sub; j < NT; j += 16) {
            float p = __expf(lg[hh * LPITCH + j] - mx);
            lg[hh * LPITCH + j] = p;
            sme += p;
        }
        for (int o = 8; o; o >>= 1) sme += __shfl_xor_sync(0xffffffffu, sme, o);
        float inv = 1.f / sme;
        for (int j = sub; j < NT; j += 16) lg[hh * LPITCH + j] *= inv;
    }
    __syncthreads();

    // ---- pass 2: PV (thread owns 4 heads x 8 stride-64 r slices) ----
    float O[4][8] = {};
    int g2 = t >> 6, u = t & 63;
    for (int tile = 0; tile < nt; tile++) {
        int j0 = tile << 4;
        __syncthreads();
        for (int j = 0; j < 16; j++) {
            int jj = j0 + j;
            if (jj < L) {
                int keyi = sel ? sel[jj] : jj;
                const float* src = &g_kv[keyi * 576];
                for (int d = t; d < 512; d += 256) kvs[j * APITCH + d] = src[d];
            }
            // pad rows: probability is 0, stale finite data is harmless
        }
        __syncthreads();
        #pragma unroll 2
        for (int j = 0; j < 16; j++) {
            float w0 = lg[(g2 * 4 + 0) * LPITCH + j0 + j];
            float w1 = lg[(g2 * 4 + 1) * LPITCH + j0 + j];
            float w2 = lg[(g2 * 4 + 2) * LPITCH + j0 + j];
            float w3 = lg[(g2 * 4 + 3) * LPITCH + j0 + j];
            #pragma unroll
            for (int r = 0; r < 8; r++) {
                float v = kvs[j * APITCH + u + r * 64];
                O[0][r] += w0 * v;
                O[1][r] += w1 * v;
                O[2][r] += w2 * v;
                O[3][r] += w3 * v;
            }
        }
    }
    #pragma unroll
    for (int i = 0; i < 4; i++)
        #pragma unroll
        for (int r = 0; r < 8; r++)
            g_attn[(q * 16 + g2 * 4 + i) * 512 + u + r * 64] = O[i][r];
}

// ------------------ launcher ------------------
extern "C" void kernel_launch(void* const* d_in, const int* in_sizes, int n_in,
                              void* d_out, int out_size)
{
    const float* q_latent = (const float*)d_in[0];
    const float* hs       = (const float*)d_in[1];
    const float* cosb     = (const float*)d_in[2];
    const float* sinb     = (const float*)d_in[3];
    const float* q_pass   = (const float*)d_in[4];
    const float* q_rot    = (const float*)d_in[5];
    const float* k_pass   = (const float*)d_in[6];
    const float* k_rot    = (const float*)d_in[7];
    /* d_in[8] position_ids: unused by reference */
    const float* kv_b     = (const float*)d_in[9];
    const float* wq_b     = (const float*)d_in[10];
    const float* wk       = (const float*)d_in[11];
    const float* k_norm   = (const float*)d_in[12];
    const float* wproj    = (const float*)d_in[13];
    const float* wproj_b  = (const float*)d_in[14];
    float* out = (float*)d_out;

    float *ql, *ckv, *wtmp, *qbuf, *attn;
    cudaGetSymbolAddress((void**)&ql,   g_ql);
    cudaGetSymbolAddress((void**)&ckv,  g_ckv);
    cudaGetSymbolAddress((void**)&wtmp, g_wtmp);
    cudaGetSymbolAddress((void**)&qbuf, g_q);
    cudaGetSymbolAddress((void**)&attn, g_attn);

    // ql = q_latent @ wq_b^T : (2048,2048)
    sgemm_k<<<dim3(32, 32, 1), 256>>>(q_latent, wq_b, ql,
        2048, 2048, 1536, 1536, 1536, 2048, 0, 0, 0, 1);
    // ckv = hs @ wk^T : (2048,128)
    sgemm_k<<<dim3(2, 32, 1), 256>>>(hs, wk, ckv,
        2048, 128, 2048, 2048, 2048, 128, 0, 0, 0, 1);
    // wtmp = hs @ wproj^T : (2048,16)
    sgemm_k<<<dim3(1, 32, 1), 256>>>(hs, wproj, wtmp,
        2048, 16, 2048, 2048, 2048, 16, 0, 0, 0, 1);
    // rope / rmsnorm / concat
    prep_k<<<2048, 128>>>(cosb, sinb, k_pass, k_rot, q_rot, k_norm, wproj_b);
    // q_abs[h] = q_pass[h] @ k_b[h] -> g_q[s][h][0:512] (batched over 16 heads)
    sgemm_k<<<dim3(8, 32, 16), 256>>>(q_pass, kv_b, qbuf,
        2048, 512, 128, 128, 512, 9216,
        2048LL * 128, 256LL * 512, 576, 0);
    // indexer scores (rows >= 1024)
    score_k<<<dim3(32, 16), 256>>>();
    // per-row top-1024
    topk_k<<<1024, 1024>>>();
    // gathered sparse attention
    cudaFuncSetAttribute(attn_k, cudaFuncAttributeMaxDynamicSharedMemorySize, ATTN_SMEM);
    attn_k<<<2048, 256, ATTN_SMEM>>>();
    // out[s][h][d] = attn[s][h][:] . v_b[h][d][:]  (batched over 16 heads)
    sgemm_k<<<dim3(2, 32, 16), 256>>>(attn, kv_b + 128 * 512, out,
        2048, 128, 512, 8192, 512, 2048,
        512, 256LL * 512, 128, 1);
}

// round 3
// speedup vs baseline: 3.2766x; 3.2766x over previous
#include <cuda_runtime.h>
#include <math.h>

#define SQ       2048
#define NH       16
#define DQK      576
#define KVL      512
#define NTOP     1024
#define SCALINGF 0.08838834764831845f  // 128^-0.5

// ------------------ device scratch (no allocation) ------------------
__device__ float g_ql  [SQ * 2048];        // q_latent @ wq_b^T
__device__ float g_ckv [SQ * 128];         // hs @ wk^T
__device__ float g_wtmp[SQ * NH];          // hs @ wproj^T
__device__ float g_iq  [SQ * NH * 128];    // index_q [s][h][128]
__device__ float g_ik  [SQ * 128];         // index_k [s][128]
__device__ float g_w   [SQ * NH];          // |wproj + b|
__device__ float g_q   [SQ * NH * DQK];    // q [s][h][576]
__device__ float g_kv  [SQ * DQK];         // kv [s][576]
__device__ float g_score[SQ * SQ];         // indexer scores (rows >=1024)
__device__ int   g_topk [SQ * NTOP];       // selected key indices (rows >=1024)
__device__ float g_attn [SQ * NH * KVL];   // softmax @ kv[:, :512]

// ------------------ cp.async helpers ------------------
__device__ __forceinline__ void cp16(void* dst, const void* src) {
    unsigned s = (unsigned)__cvta_generic_to_shared(dst);
    asm volatile("cp.async.cg.shared.global [%0], [%1], 16;\n" :: "r"(s), "l"(src));
}
__device__ __forceinline__ void cp_commit() {
    asm volatile("cp.async.commit_group;\n" ::: "memory");
}
__device__ __forceinline__ void cp_wait1() {
    asm volatile("cp.async.wait_group 1;\n" ::: "memory");
}

// ------------------ generic batched SGEMM: C = A @ B(^T) ------------------
__global__ __launch_bounds__(256) void sgemm_k(
    const float* __restrict__ A, const float* __restrict__ B, float* __restrict__ C,
    int M, int N, int K, int lda, int ldb, int ldc,
    long long sA, long long sB, long long sC, int transB)
{
    A += (long long)blockIdx.z * sA;
    B += (long long)blockIdx.z * sB;
    C += (long long)blockIdx.z * sC;
    __shared__ float As[16][65];
    __shared__ float Bs[16][65];
    int tid = threadIdx.x, tx = tid & 15, ty = tid >> 4;
    int m0 = blockIdx.y * 64, n0 = blockIdx.x * 64;
    float acc[4][4] = {};
    for (int k0 = 0; k0 < K; k0 += 16) {
        for (int e = tid; e < 1024; e += 256) {
            int m = e >> 4, k = e & 15;
            int gm = m0 + m, gk = k0 + k;
            As[k][m] = (gm < M && gk < K) ? A[(long long)gm * lda + gk] : 0.f;
        }
        if (transB) {
            for (int e = tid; e < 1024; e += 256) {
                int n = e >> 4, k = e & 15;
                int gn = n0 + n, gk = k0 + k;
                Bs[k][n] = (gn < N && gk < K) ? B[(long long)gn * ldb + gk] : 0.f;
            }
        } else {
            for (int e = tid; e < 1024; e += 256) {
                int k = e >> 6, n = e & 63;
                int gn = n0 + n, gk = k0 + k;
                Bs[k][n] = (gn < N && gk < K) ? B[(long long)gk * ldb + gn] : 0.f;
            }
        }
        __syncthreads();
        #pragma unroll
        for (int kk = 0; kk < 16; kk++) {
            float a[4], b[4];
            #pragma unroll
            for (int i = 0; i < 4; i++) a[i] = As[kk][ty * 4 + i];
            #pragma unroll
            for (int j = 0; j < 4; j++) b[j] = Bs[kk][tx * 4 + j];
            #pragma unroll
            for (int i = 0; i < 4; i++)
                #pragma unroll
                for (int j = 0; j < 4; j++) acc[i][j] += a[i] * b[j];
        }
        __syncthreads();
    }
    #pragma unroll
    for (int i = 0; i < 4; i++) {
        int gm = m0 + ty * 4 + i;
        if (gm >= M) continue;
        #pragma unroll
        for (int j = 0; j < 4; j++) {
            int gn = n0 + tx * 4 + j;
            if (gn >= N) continue;
            C[(long long)gm * ldc + gn] = acc[i][j];
        }
    }
}

// ------------------ prep: rope / rmsnorm / concats ------------------
__global__ __launch_bounds__(128) void prep_k(
    const float* __restrict__ cosb, const float* __restrict__ sinb,
    const float* __restrict__ k_pass, const float* __restrict__ k_rot,
    const float* __restrict__ q_rot, const float* __restrict__ k_norm_w,
    const float* __restrict__ wproj_b)
{
    int s = blockIdx.x, t = threadIdx.x;
    const float* cs = cosb + s * 64;
    const float* sn = sinb + s * 64;
    if (t < 32) {
        float x0 = g_ckv[s * 128 + 2 * t], x1 = g_ckv[s * 128 + 2 * t + 1];
        g_ik[s * 128 + t]      = x0 * cs[t]      - x1 * sn[t];
        g_ik[s * 128 + 32 + t] = x1 * cs[32 + t] + x0 * sn[32 + t];
    }
    __shared__ float partials[4];
    float v = 0.f;
    if (t < 64) { float x = g_ckv[s * 128 + 64 + t]; v = x * x; }
    for (int o = 16; o > 0; o >>= 1) v += __shfl_xor_sync(0xffffffffu, v, o);
    if ((t & 31) == 0) partials[t >> 5] = v;
    __syncthreads();
    float var = (partials[0] + partials[1]) * (1.f / 64.f);
    float inv = rsqrtf(var + 1e-6f);
    if (t < 64)
        g_ik[s * 128 + 64 + t] = g_ckv[s * 128 + 64 + t] * inv * k_norm_w[t];
    for (int u = t; u < 16 * 32; u += 128) {
        int h = u >> 5, i = u & 31;
        float x0 = g_ql[s * 2048 + h * 128 + 2 * i];
        float x1 = g_ql[s * 2048 + h * 128 + 2 * i + 1];
        g_iq[(s * 16 + h) * 128 + i]      = x0 * cs[i]      - x1 * sn[i];
        g_iq[(s * 16 + h) * 128 + 32 + i] = x1 * cs[32 + i] + x0 * sn[32 + i];
    }
    for (int u = t; u < 16 * 64; u += 128) {
        int h = u >> 6, i = u & 63;
        g_iq[(s * 16 + h) * 128 + 64 + i] = g_ql[s * 2048 + h * 128 + 64 + i];
    }
    if (t < 16) g_w[s * 16 + t] = fabsf(g_wtmp[s * 16 + t] + wproj_b[t]);
    for (int u = t; u < 512; u += 128) g_kv[s * 576 + u] = k_pass[s * 512 + u];
    if (t < 64) g_kv[s * 576 + 512 + t] = k_rot[s * 64 + t];
    for (int u = t; u < 16 * 64; u += 128) {
        int h = u >> 6, j = u & 63;
        g_q[(s * 16 + h) * 576 + 512 + j] = q_rot[(h * 2048 + s) * 64 + j];
    }
}

// ------------------ indexer scores for rows q >= 1024 ------------------
__global__ __launch_bounds__(256) void score_k()
{
    __shared__ float Qs[32][65];
    __shared__ float Ks[32][65];
    __shared__ float ws[64];
    int q0 = 1024 + blockIdx.y * 64;
    int k0 = blockIdx.x * 64;
    if (k0 > q0 + 63) return;
    int tid = threadIdx.x, tx = tid & 15, ty = tid >> 4;
    float acc[4][4] = {};
    for (int h = 0; h < 16; h++) {
        float dacc[4][4] = {};
        for (int d0 = 0; d0 < 128; d0 += 32) {
            __syncthreads();
            for (int e = tid; e < 2048; e += 256) {
                int m = e >> 5, dd = e & 31;
                Qs[dd][m] = g_iq[((q0 + m) * 16 + h) * 128 + d0 + dd];
                Ks[dd][m] = g_ik[(k0 + m) * 128 + d0 + dd];
            }
            __syncthreads();
            #pragma unroll
            for (int dd = 0; dd < 32; dd++) {
                float a[4], b[4];
                #pragma unroll
                for (int i = 0; i < 4; i++) a[i] = Qs[dd][ty * 4 + i];
                #pragma unroll
                for (int j = 0; j < 4; j++) b[j] = Ks[dd][tx * 4 + j];
                #pragma unroll
                for (int i = 0; i < 4; i++)
                    #pragma unroll
                    for (int j = 0; j < 4; j++) dacc[i][j] += a[i] * b[j];
            }
        }
        __syncthreads();
        if (tid < 64) ws[tid] = g_w[(q0 + tid) * 16 + h];
        __syncthreads();
        #pragma unroll
        for (int i = 0; i < 4; i++)
            #pragma unroll
            for (int j = 0; j < 4; j++)
                acc[i][j] += ws[ty * 4 + i] * fmaxf(dacc[i][j] * SCALINGF, 0.f);
    }
    #pragma unroll
    for (int i = 0; i < 4; i++)
        #pragma unroll
        for (int j = 0; j < 4; j++)
            g_score[(q0 + ty * 4 + i) * 2048 + k0 + tx * 4 + j] = acc[i][j];
}

// ------------------ top-1024 per row (bitonic, jax tie-break) ------------------
__global__ __launch_bounds__(1024) void topk_k()
{
    __shared__ unsigned long long key[2048];
    int q = 1024 + blockIdx.x;
    int t = threadIdx.x;
    for (int u = t; u < 2048; u += 1024) {
        unsigned long long kk = 0ull;
        if (u <= q) {
            unsigned int b = __float_as_uint(g_score[q * 2048 + u]);  // score >= 0
            kk = ((unsigned long long)b << 32) | (unsigned int)(~u);
        }
        key[u] = kk;
    }
    __syncthreads();
    for (int ks = 2; ks <= 2048; ks <<= 1) {
        for (int j = ks >> 1; j > 0; j >>= 1) {
            int i = ((t & ~(j - 1)) << 1) | (t & (j - 1));
            int p = i | j;
            bool desc = (i & ks) == 0;
            unsigned long long a = key[i], b = key[p];
            if ((a < b) == desc) { key[i] = b; key[p] = a; }
            __syncthreads();
        }
    }
    g_topk[q * 1024 + t] = (int)(~(unsigned int)(key[t] & 0xFFFFFFFFull));
}

// ------------------ single-pass flash attention with gathered keys ------------------
// smem: q[16*576] + kv[2][32*576] + s[16*32] + p[16*32] + f[16] + l[16]
#define ATTN_SMEM ((16*576 + 2*32*576 + 16*32*2 + 32) * 4)

__global__ __launch_bounds__(512) void attn_k()
{
    extern __shared__ float sm[];
    float* qsm = sm;                    // 9216
    float* kvb = qsm + 16 * 576;        // 2 * 18432
    float* s_s = kvb + 2 * 32 * 576;    // 512
    float* p_s = s_s + 512;             // 512
    float* f_s = p_s + 512;             // 16
    float* l_s = f_s + 16;              // 16

    int q = blockIdx.x, t = threadIdx.x;
    int L = (q < 1024) ? (q + 1) : 1024;
    const int* sel = (q < 1024) ? (const int*)0 : &g_topk[q * 1024];
    int nt = (L + 31) >> 5;

    // load q row (16 heads x 576) via float4
    {
        const float4* qg = (const float4*)&g_q[q * 16 * 576];
        float4* q4 = (float4*)qsm;
        for (int i = t; i < 2304; i += 512) q4[i] = qg[i];
    }

    int wid = t >> 5, lane = t & 31;
    int h0 = 2 * (wid & 7);            // logits heads h0, h0+1
    int kh = wid >> 3;                 // key half: 0 -> keys 0..15, 1 -> 16..31
    int pg = t >> 7;                   // PV head group (4 heads)
    int d4 = t & 127;                  // PV float4 dim index (dims d4*4..+3 < 512)
    int gj = t >> 4, gf = t & 15;      // gather: row, float4 lane

    __syncthreads();

    // q into registers for logits (2 heads x 18 strided dims)
    float qr0[18], qr1[18];
    #pragma unroll
    for (int r = 0; r < 18; r++) {
        qr0[r] = qsm[h0 * 576 + lane + 32 * r];
        qr1[r] = qsm[(h0 + 1) * 576 + lane + 32 * r];
    }

    float4 acc0 = {0,0,0,0}, acc1 = {0,0,0,0}, acc2 = {0,0,0,0}, acc3 = {0,0,0,0};
    float m_cur = -1e30f, l_cur = 0.f;

    // gather lambda behavior (manual): tile -> buf
    // prefetch tile 0
    {
        int jj = gj;
        float* dst = kvb + gj * 576;
        if (jj < L) {
            int keyi = sel ? sel[jj] : jj;
            const float* src = &g_kv[keyi * 576];
            #pragma unroll
            for (int i = 0; i < 9; i++) {
                int f4 = gf + 16 * i;
                cp16(dst + f4 * 4, src + f4 * 4);
            }
        } else {
            float4 z = {0,0,0,0};
            #pragma unroll
            for (int i = 0; i < 9; i++) ((float4*)dst)[gf + 16 * i] = z;
        }
    }
    cp_commit();

    for (int tile = 0; tile < nt; tile++) {
        int buf = tile & 1;
        // prefetch next tile into other buffer
        if (tile + 1 < nt) {
            int jj = (tile + 1) * 32 + gj;
            float* dst = kvb + (buf ^ 1) * 18432 + gj * 576;
            if (jj < L) {
                int keyi = sel ? sel[jj] : jj;
                const float* src = &g_kv[keyi * 576];
                #pragma unroll
                for (int i = 0; i < 9; i++) {
                    int f4 = gf + 16 * i;
                    cp16(dst + f4 * 4, src + f4 * 4);
                }
            } else {
                float4 z = {0,0,0,0};
                #pragma unroll
                for (int i = 0; i < 9; i++) ((float4*)dst)[gf + 16 * i] = z;
            }
        }
        cp_commit();
        cp_wait1();           // current tile's group complete
        __syncthreads();      // visible to all threads

        // ---- logits: warp computes 2 heads x 16 keys over strided dims ----
        {
            const float* kb = kvb + buf * 18432 + kh * 16 * 576;
            float pa0[16], pa1[16];
            #pragma unroll
            for (int kk = 0; kk < 16; kk++) {
                const float* row = kb + kk * 576 + lane;
                float a0 = 0.f, a1 = 0.f;
                #pragma unroll
                for (int r = 0; r < 18; r++) {
                    float v = row[32 * r];
                    a0 += qr0[r] * v;
                    a1 += qr1[r] * v;
                }
                pa0[kk] = a0; pa1[kk] = a1;
            }
            #pragma unroll
            for (int kk = 0; kk < 16; kk++) {
                float a0 = pa0[kk], a1 = pa1[kk];
                #pragma unroll
                for (int o = 16; o > 0; o >>= 1) {
                    a0 += __shfl_xor_sync(0xffffffffu, a0, o);
                    a1 += __shfl_xor_sync(0xffffffffu, a1, o);
                }
                if (lane == kk) {
                    s_s[h0 * 32 + kh * 16 + kk] = a0;
                    s_s[(h0 + 1) * 32 + kh * 16 + kk] = a1;
                }
            }
        }
        __syncthreads();

        // ---- online softmax: warp wid handles head wid, lane = key ----
        {
            float val = s_s[wid * 32 + lane] * SCALINGF;
            int jj = tile * 32 + lane;
            val = (jj < L) ? val : -1e30f;
            float mx = val;
            #pragma unroll
            for (int o = 16; o > 0; o >>= 1)
                mx = fmaxf(mx, __shfl_xor_sync(0xffffffffu, mx, o));
            float m_new = fmaxf(m_cur, mx);
            float factor = __expf(m_cur - m_new);
            float p = __expf(val - m_new);
            float ps = p;
            #pragma unroll
            for (int o = 16; o > 0; o >>= 1)
                ps += __shfl_xor_sync(0xffffffffu, ps, o);
            l_cur = l_cur * factor + ps;
            m_cur = m_new;
            p_s[wid * 32 + lane] = p;
            if (lane == 0) f_s[wid] = factor;
        }
        __syncthreads();

        // ---- PV: thread owns 4 heads x 4 dims (float4), rescale + accumulate ----
        {
            float fa = f_s[4 * pg + 0], fb = f_s[4 * pg + 1];
            float fc = f_s[4 * pg + 2], fd = f_s[4 * pg + 3];
            acc0.x *= fa; acc0.y *= fa; acc0.z *= fa; acc0.w *= fa;
            acc1.x *= fb; acc1.y *= fb; acc1.z *= fb; acc1.w *= fb;
            acc2.x *= fc; acc2.y *= fc; acc2.z *= fc; acc2.w *= fc;
            acc3.x *= fd; acc3.y *= fd; acc3.z *= fd; acc3.w *= fd;
            const float4* kv4 = (const float4*)(kvb + buf * 18432);
            #pragma unroll 4
            for (int kk = 0; kk < 32; kk++) {
                float4 v = kv4[kk * 144 + d4];
                float p0 = p_s[(4 * pg + 0) * 32 + kk];
                float p1 = p_s[(4 * pg + 1) * 32 + kk];
                float p2 = p_s[(4 * pg + 2) * 32 + kk];
                float p3 = p_s[(4 * pg + 3) * 32 + kk];
                acc0.x += p0 * v.x; acc0.y += p0 * v.y; acc0.z += p0 * v.z; acc0.w += p0 * v.w;
                acc1.x += p1 * v.x; acc1.y += p1 * v.y; acc1.z += p1 * v.z; acc1.w += p1 * v.w;
                acc2.x += p2 * v.x; acc2.y += p2 * v.y; acc2.z += p2 * v.z; acc2.w += p2 * v.w;
                acc3.x += p3 * v.x; acc3.y += p3 * v.y; acc3.z += p3 * v.z; acc3.w += p3 * v.w;
            }
        }
        __syncthreads();   // protect buffer before tile+2 prefetch overwrites
    }

    if (lane == 0) l_s[wid] = l_cur;
    __syncthreads();

    {
        float4* outp = (float4*)g_attn;
        float i0 = 1.f / l_s[4 * pg + 0];
        float i1 = 1.f / l_s[4 * pg + 1];
        float i2 = 1.f / l_s[4 * pg + 2];
        float i3 = 1.f / l_s[4 * pg + 3];
        float4 o;
        o.x = acc0.x * i0; o.y = acc0.y * i0; o.z = acc0.z * i0; o.w = acc0.w * i0;
        outp[(q * 16 + 4 * pg + 0) * 128 + d4] = o;
        o.x = acc1.x * i1; o.y = acc1.y * i1; o.z = acc1.z * i1; o.w = acc1.w * i1;
        outp[(q * 16 + 4 * pg + 1) * 128 + d4] = o;
        o.x = acc2.x * i2; o.y = acc2.y * i2; o.z = acc2.z * i2; o.w = acc2.w * i2;
        outp[(q * 16 + 4 * pg + 2) * 128 + d4] = o;
        o.x = acc3.x * i3; o.y = acc3.y * i3; o.z = acc3.z * i3; o.w = acc3.w * i3;
        outp[(q * 16 + 4 * pg + 3) * 128 + d4] = o;
    }
}

// ------------------ launcher ------------------
extern "C" void kernel_launch(void* const* d_in, const int* in_sizes, int n_in,
                              void* d_out, int out_size)
{
    const float* q_latent = (const float*)d_in[0];
    const float* hs       = (const float*)d_in[1];
    const float* cosb     = (const float*)d_in[2];
    const float* sinb     = (const float*)d_in[3];
    const float* q_pass   = (const float*)d_in[4];
    const float* q_rot    = (const float*)d_in[5];
    const float* k_pass   = (const float*)d_in[6];
    const float* k_rot    = (const float*)d_in[7];
    const float* kv_b     = (const float*)d_in[9];
    const float* wq_b     = (const float*)d_in[10];
    const float* wk       = (const float*)d_in[11];
    const float* k_norm   = (const float*)d_in[12];
    const float* wproj    = (const float*)d_in[13];
    const float* wproj_b  = (const float*)d_in[14];
    float* out = (float*)d_out;

    float *ql, *ckv, *wtmp, *qbuf, *attn;
    cudaGetSymbolAddress((void**)&ql,   g_ql);
    cudaGetSymbolAddress((void**)&ckv,  g_ckv);
    cudaGetSymbolAddress((void**)&wtmp, g_wtmp);
    cudaGetSymbolAddress((void**)&qbuf, g_q);
    cudaGetSymbolAddress((void**)&attn, g_attn);

    sgemm_k<<<dim3(32, 32, 1), 256>>>(q_latent, wq_b, ql,
        2048, 2048, 1536, 1536, 1536, 2048, 0, 0, 0, 1);
    sgemm_k<<<dim3(2, 32, 1), 256>>>(hs, wk, ckv,
        2048, 128, 2048, 2048, 2048, 128, 0, 0, 0, 1);
    sgemm_k<<<dim3(1, 32, 1), 256>>>(hs, wproj, wtmp,
        2048, 16, 2048, 2048, 2048, 16, 0, 0, 0, 1);
    prep_k<<<2048, 128>>>(cosb, sinb, k_pass, k_rot, q_rot, k_norm, wproj_b);
    sgemm_k<<<dim3(8, 32, 16), 256>>>(q_pass, kv_b, qbuf,
        2048, 512, 128, 128, 512, 9216,
        2048LL * 128, 256LL * 512, 576, 0);
    score_k<<<dim3(32, 16), 256>>>();
    topk_k<<<1024, 1024>>>();
    cudaFuncSetAttribute(attn_k, cudaFuncAttributeMaxDynamicSharedMemorySize, ATTN_SMEM);
    attn_k<<<2048, 512, ATTN_SMEM>>>();
    sgemm_k<<<dim3(2, 32, 16), 256>>>(attn, kv_b + 128 * 512, out,
        2048, 128, 512, 8192, 512, 2048,
        512, 256LL * 512, 128, 1);
}

// round 5
// speedup vs baseline: 4.4743x; 1.3655x over previous
#include <cuda_runtime.h>
#include <stdint.h>
#include <math.h>

#define SQ       2048
#define NH       16
#define DQK      576
#define KVL      512
#define NTOP     1024
#define SCALINGF 0.08838834764831845f  // 128^-0.5

// ------------------ device scratch (no allocation) ------------------
__device__ float g_ql  [SQ * 2048];
__device__ float g_ckv [SQ * 128];
__device__ float g_wtmp[SQ * NH];
__device__ float g_iq  [SQ * NH * 128];
__device__ float g_ik  [SQ * 128];
__device__ float g_w   [SQ * NH];
__device__ float g_q   [SQ * NH * DQK];
__device__ float g_kv  [SQ * DQK];
__device__ float g_score[SQ * SQ];
__device__ int   g_topk [SQ * NTOP];
__device__ float g_attn [SQ * NH * KVL];

// ------------------ cp.async helpers ------------------
__device__ __forceinline__ void cp16(void* dst, const void* src) {
    unsigned s = (unsigned)__cvta_generic_to_shared(dst);
    asm volatile("cp.async.cg.shared.global [%0], [%1], 16;\n" :: "r"(s), "l"(src));
}
__device__ __forceinline__ void cp_commit() {
    asm volatile("cp.async.commit_group;\n" ::: "memory");
}
__device__ __forceinline__ void cp_wait1() {
    asm volatile("cp.async.wait_group 1;\n" ::: "memory");
}

// ------------------ tf32 mma helpers ------------------
__device__ __forceinline__ uint32_t cvt_tf32(float x) {
    uint32_t r; asm("cvt.rna.tf32.f32 %0, %1;" : "=r"(r) : "f"(x)); return r;
}
__device__ __forceinline__ void mma_tf32(float* c,
    uint32_t a0, uint32_t a1, uint32_t a2, uint32_t a3,
    uint32_t b0, uint32_t b1)
{
    asm volatile(
        "mma.sync.aligned.m16n8k8.row.col.f32.tf32.tf32.f32 "
        "{%0,%1,%2,%3}, {%4,%5,%6,%7}, {%8,%9}, {%0,%1,%2,%3};\n"
        : "+f"(c[0]), "+f"(c[1]), "+f"(c[2]), "+f"(c[3])
        : "r"(a0), "r"(a1), "r"(a2), "r"(a3), "r"(b0), "r"(b1));
}

// ------------------ generic batched SGEMM: C = A @ B(^T) ------------------
__global__ __launch_bounds__(256) void sgemm_k(
    const float* __restrict__ A, const float* __restrict__ B, float* __restrict__ C,
    int M, int N, int K, int lda, int ldb, int ldc,
    long long sA, long long sB, long long sC, int transB)
{
    A += (long long)blockIdx.z * sA;
    B += (long long)blockIdx.z * sB;
    C += (long long)blockIdx.z * sC;
    __shared__ float As[16][65];
    __shared__ float Bs[16][65];
    int tid = threadIdx.x, tx = tid & 15, ty = tid >> 4;
    int m0 = blockIdx.y * 64, n0 = blockIdx.x * 64;
    float acc[4][4] = {};
    for (int k0 = 0; k0 < K; k0 += 16) {
        for (int e = tid; e < 1024; e += 256) {
            int m = e >> 4, k = e & 15;
            int gm = m0 + m, gk = k0 + k;
            As[k][m] = (gm < M && gk < K) ? A[(long long)gm * lda + gk] : 0.f;
        }
        if (transB) {
            for (int e = tid; e < 1024; e += 256) {
                int n = e >> 4, k = e & 15;
                int gn = n0 + n, gk = k0 + k;
                Bs[k][n] = (gn < N && gk < K) ? B[(long long)gn * ldb + gk] : 0.f;
            }
        } else {
            for (int e = tid; e < 1024; e += 256) {
                int k = e >> 6, n = e & 63;
                int gn = n0 + n, gk = k0 + k;
                Bs[k][n] = (gn < N && gk < K) ? B[(long long)gk * ldb + gn] : 0.f;
            }
        }
        __syncthreads();
        #pragma unroll
        for (int kk = 0; kk < 16; kk++) {
            float a[4], b[4];
            #pragma unroll
            for (int i = 0; i < 4; i++) a[i] = As[kk][ty * 4 + i];
            #pragma unroll
            for (int j = 0; j < 4; j++) b[j] = Bs[kk][tx * 4 + j];
            #pragma unroll
            for (int i = 0; i < 4; i++)
                #pragma unroll
                for (int j = 0; j < 4; j++) acc[i][j] += a[i] * b[j];
        }
        __syncthreads();
    }
    #pragma unroll
    for (int i = 0; i < 4; i++) {
        int gm = m0 + ty * 4 + i;
        if (gm >= M) continue;
        #pragma unroll
        for (int j = 0; j < 4; j++) {
            int gn = n0 + tx * 4 + j;
            if (gn >= N) continue;
            C[(long long)gm * ldc + gn] = acc[i][j];
        }
    }
}

// ------------------ prep: rope / rmsnorm / concats ------------------
__global__ __launch_bounds__(128) void prep_k(
    const float* __restrict__ cosb, const float* __restrict__ sinb,
    const float* __restrict__ k_pass, const float* __restrict__ k_rot,
    const float* __restrict__ q_rot, const float* __restrict__ k_norm_w,
    const float* __restrict__ wproj_b)
{
    int s = blockIdx.x, t = threadIdx.x;
    const float* cs = cosb + s * 64;
    const float* sn = sinb + s * 64;
    if (t < 32) {
        float x0 = g_ckv[s * 128 + 2 * t], x1 = g_ckv[s * 128 + 2 * t + 1];
        g_ik[s * 128 + t]      = x0 * cs[t]      - x1 * sn[t];
        g_ik[s * 128 + 32 + t] = x1 * cs[32 + t] + x0 * sn[32 + t];
    }
    __shared__ float partials[4];
    float v = 0.f;
    if (t < 64) { float x = g_ckv[s * 128 + 64 + t]; v = x * x; }
    for (int o = 16; o > 0; o >>= 1) v += __shfl_xor_sync(0xffffffffu, v, o);
    if ((t & 31) == 0) partials[t >> 5] = v;
    __syncthreads();
    float var = (partials[0] + partials[1]) * (1.f / 64.f);
    float inv = rsqrtf(var + 1e-6f);
    if (t < 64)
        g_ik[s * 128 + 64 + t] = g_ckv[s * 128 + 64 + t] * inv * k_norm_w[t];
    for (int u = t; u < 16 * 32; u += 128) {
        int h = u >> 5, i = u & 31;
        float x0 = g_ql[s * 2048 + h * 128 + 2 * i];
        float x1 = g_ql[s * 2048 + h * 128 + 2 * i + 1];
        g_iq[(s * 16 + h) * 128 + i]      = x0 * cs[i]      - x1 * sn[i];
        g_iq[(s * 16 + h) * 128 + 32 + i] = x1 * cs[32 + i] + x0 * sn[32 + i];
    }
    for (int u = t; u < 16 * 64; u += 128) {
        int h = u >> 6, i = u & 63;
        g_iq[(s * 16 + h) * 128 + 64 + i] = g_ql[s * 2048 + h * 128 + 64 + i];
    }
    if (t < 16) g_w[s * 16 + t] = fabsf(g_wtmp[s * 16 + t] + wproj_b[t]);
    for (int u = t; u < 512; u += 128) g_kv[s * 576 + u] = k_pass[s * 512 + u];
    if (t < 64) g_kv[s * 576 + 512 + t] = k_rot[s * 64 + t];
    for (int u = t; u < 16 * 64; u += 128) {
        int h = u >> 6, j = u & 63;
        g_q[(s * 16 + h) * 576 + 512 + j] = q_rot[(h * 2048 + s) * 64 + j];
    }
}

// ------------------ indexer scores for rows q >= 1024 (fp32, exact) ------------------
__global__ __launch_bounds__(256) void score_k()
{
    __shared__ float Qs[32][65];
    __shared__ float Ks[32][65];
    __shared__ float ws[64];
    int q0 = 1024 + blockIdx.y * 64;
    int k0 = blockIdx.x * 64;
    if (k0 > q0 + 63) return;
    int tid = threadIdx.x, tx = tid & 15, ty = tid >> 4;
    float acc[4][4] = {};
    for (int h = 0; h < 16; h++) {
        float dacc[4][4] = {};
        for (int d0 = 0; d0 < 128; d0 += 32) {
            __syncthreads();
            for (int e = tid; e < 2048; e += 256) {
                int m = e >> 5, dd = e & 31;
                Qs[dd][m] = g_iq[((q0 + m) * 16 + h) * 128 + d0 + dd];
                Ks[dd][m] = g_ik[(k0 + m) * 128 + d0 + dd];
            }
            __syncthreads();
            #pragma unroll
            for (int dd = 0; dd < 32; dd++) {
                float a[4], b[4];
                #pragma unroll
                for (int i = 0; i < 4; i++) a[i] = Qs[dd][ty * 4 + i];
                #pragma unroll
                for (int j = 0; j < 4; j++) b[j] = Ks[dd][tx * 4 + j];
                #pragma unroll
                for (int i = 0; i < 4; i++)
                    #pragma unroll
                    for (int j = 0; j < 4; j++) dacc[i][j] += a[i] * b[j];
            }
        }
        __syncthreads();
        if (tid < 64) ws[tid] = g_w[(q0 + tid) * 16 + h];
        __syncthreads();
        #pragma unroll
        for (int i = 0; i < 4; i++)
            #pragma unroll
            for (int j = 0; j < 4; j++)
                acc[i][j] += ws[ty * 4 + i] * fmaxf(dacc[i][j] * SCALINGF, 0.f);
    }
    #pragma unroll
    for (int i = 0; i < 4; i++)
        #pragma unroll
        for (int j = 0; j < 4; j++)
            g_score[(q0 + ty * 4 + i) * 2048 + k0 + tx * 4 + j] = acc[i][j];
}

// ------------------ top-1024 per row (bitonic, jax tie-break) ------------------
__global__ __launch_bounds__(1024) void topk_k()
{
    __shared__ unsigned long long key[2048];
    int q = 1024 + blockIdx.x;
    int t = threadIdx.x;
    for (int u = t; u < 2048; u += 1024) {
        unsigned long long kk = 0ull;
        if (u <= q) {
            unsigned int b = __float_as_uint(g_score[q * 2048 + u]);  // score >= 0
            kk = ((unsigned long long)b << 32) | (unsigned int)(~u);
        }
        key[u] = kk;
    }
    __syncthreads();
    for (int ks = 2; ks <= 2048; ks <<= 1) {
        for (int j = ks >> 1; j > 0; j >>= 1) {
            int i = ((t & ~(j - 1)) << 1) | (t & (j - 1));
            int p = i | j;
            bool desc = (i & ks) == 0;
            unsigned long long a = key[i], b = key[p];
            if ((a < b) == desc) { key[i] = b; key[p] = a; }
            __syncthreads();
        }
    }
    g_topk[q * 1024 + t] = (int)(~(unsigned int)(key[t] & 0xFFFFFFFFull));
}

// ------------------ single-pass flash attention, tf32 tensor cores ------------------
#define KP 580                 // kv smem pitch (floats)
#define QP 580                 // q smem pitch
#define PP 36                  // p smem pitch
#define KVBUF (32 * KP)        // 18560 floats per buffer
// smem: q[16*QP] + kv[2*32*KP] + part[4*16*33] + p[16*PP] + f[16] + l[16]
#define ATTN_SMEM ((16*QP + 2*KVBUF + 4*16*33 + 16*PP + 32) * 4)

__global__ __launch_bounds__(512) void attn_k()
{
    extern __shared__ float sm[];
    float* qsm  = sm;                       // 16*580
    float* kvb  = qsm + 16 * QP;            // 2*18560
    float* part = kvb + 2 * KVBUF;          // 4*16*33 = 2112
    float* p_s  = part + 2112;              // 16*36
    float* f_s  = p_s + 16 * PP;            // 16
    float* l_s  = f_s + 16;                 // 16

    int q = blockIdx.x, t = threadIdx.x;
    int L = (q < 1024) ? (q + 1) : 1024;
    const int* sel = (q < 1024) ? (const int*)0 : &g_topk[q * 1024];
    int nt = (L + 31) >> 5;

    int wid = t >> 5, lane = t & 31;
    int g = lane >> 2, tg = lane & 3;       // mma group / thread-in-group
    int gj = t >> 4, gf = t & 15;           // gather: row, float4 lane

    // load q row (16 heads x 576), pre-rounded to tf32
    {
        const float4* qg = (const float4*)&g_q[q * 16 * 576];
        for (int i = t; i < 2304; i += 512) {
            int row = i / 144, f4 = i % 144;
            float4 v = qg[i];
            float* d = qsm + row * QP + f4 * 4;
            d[0] = __uint_as_float(cvt_tf32(v.x));
            d[1] = __uint_as_float(cvt_tf32(v.y));
            d[2] = __uint_as_float(cvt_tf32(v.z));
            d[3] = __uint_as_float(cvt_tf32(v.w));
        }
    }

    // PV accumulators: warp owns dims [wid*32, wid*32+32), rows g and g+8
    float acc[4][4] = {};
    float m_cur = -1e30f, l_cur = 0.f;

    // prefetch tile 0
    {
        float* dst = kvb + gj * KP;
        if (gj < L) {
            int keyi = sel ? sel[gj] : gj;
            const float* src = &g_kv[keyi * 576];
            #pragma unroll
            for (int i = 0; i < 9; i++) {
                int f4 = gf + 16 * i;
                cp16(dst + f4 * 4, src + f4 * 4);
            }
        } else {
            float4 z = {0, 0, 0, 0};
            #pragma unroll
            for (int i = 0; i < 9; i++)
                *(float4*)(dst + (gf + 16 * i) * 4) = z;
        }
    }
    cp_commit();
    __syncthreads();   // qsm ready (also covers zero-fill visibility)

    int nc = wid & 3;       // QK n-chunk (keys nc*8..nc*8+7)
    int kq = wid >> 2;      // QK k-quarter (dims kq*144..)

    for (int tile = 0; tile < nt; tile++) {
        int buf = tile & 1;
        float* kvs = kvb + buf * KVBUF;
        // prefetch next tile
        if (tile + 1 < nt) {
            int jj = (tile + 1) * 32 + gj;
            float* dst = kvb + (buf ^ 1) * KVBUF + gj * KP;
            if (jj < L) {
                int keyi = sel ? sel[jj] : jj;
                const float* src = &g_kv[keyi * 576];
                #pragma unroll
                for (int i = 0; i < 9; i++) {
                    int f4 = gf + 16 * i;
                    cp16(dst + f4 * 4, src + f4 * 4);
                }
            } else {
                float4 z = {0, 0, 0, 0};
                #pragma unroll
                for (int i = 0; i < 9; i++)
                    *(float4*)(dst + (gf + 16 * i) * 4) = z;
            }
        }
        cp_commit();
        cp_wait1();
        __syncthreads();   // kvs(buf) ready for all

        // ---- QK: warp computes C[16 heads][8 keys] over its k-quarter ----
        {
            float c[4] = {0, 0, 0, 0};
            #pragma unroll
            for (int kc = 0; kc < 18; kc++) {
                int k0 = kq * 144 + kc * 8;
                uint32_t a0 = __float_as_uint(qsm[g * QP + k0 + tg]);
                uint32_t a1 = __float_as_uint(qsm[(g + 8) * QP + k0 + tg]);
                uint32_t a2 = __float_as_uint(qsm[g * QP + k0 + tg + 4]);
                uint32_t a3 = __float_as_uint(qsm[(g + 8) * QP + k0 + tg + 4]);
                uint32_t b0 = cvt_tf32(kvs[(nc * 8 + g) * KP + k0 + tg]);
                uint32_t b1 = cvt_tf32(kvs[(nc * 8 + g) * KP + k0 + tg + 4]);
                mma_tf32(c, a0, a1, a2, a3, b0, b1);
            }
            // partials: part[kq][head][key] with pitch 33
            float* pp = part + kq * 528;
            pp[g * 33 + nc * 8 + 2 * tg]           = c[0];
            pp[g * 33 + nc * 8 + 2 * tg + 1]       = c[1];
            pp[(g + 8) * 33 + nc * 8 + 2 * tg]     = c[2];
            pp[(g + 8) * 33 + nc * 8 + 2 * tg + 1] = c[3];
        }
        __syncthreads();

        // ---- reduce + online softmax: warp wid = head wid, lane = key ----
        {
            float val = part[wid * 33 + lane] + part[528 + wid * 33 + lane]
                      + part[1056 + wid * 33 + lane] + part[1584 + wid * 33 + lane];
            val *= SCALINGF;
            int jj = tile * 32 + lane;
            val = (jj < L) ? val : -1e30f;
            float mx = val;
            #pragma unroll
            for (int o = 16; o > 0; o >>= 1)
                mx = fmaxf(mx, __shfl_xor_sync(0xffffffffu, mx, o));
            float m_new = fmaxf(m_cur, mx);
            float factor = __expf(m_cur - m_new);
            float p = __uint_as_float(cvt_tf32(__expf(val - m_new)));
            float ps = p;
            #pragma unroll
            for (int o = 16; o > 0; o >>= 1)
                ps += __shfl_xor_sync(0xffffffffu, ps, o);
            l_cur = l_cur * factor + ps;
            m_cur = m_new;
            p_s[wid * PP + lane] = p;
            if (lane == 0) f_s[wid] = factor;
        }
        __syncthreads();

        // ---- PV: warp owns 32 dims; rescale + mma-accumulate ----
        {
            int nb = wid * 32;
            float fg = f_s[g], fg8 = f_s[g + 8];
            #pragma unroll
            for (int c2 = 0; c2 < 4; c2++) {
                acc[c2][0] *= fg;  acc[c2][1] *= fg;
                acc[c2][2] *= fg8; acc[c2][3] *= fg8;
            }
            #pragma unroll
            for (int kc = 0; kc < 4; kc++) {
                uint32_t a0 = __float_as_uint(p_s[g * PP + kc * 8 + tg]);
                uint32_t a1 = __float_as_uint(p_s[(g + 8) * PP + kc * 8 + tg]);
                uint32_t a2 = __float_as_uint(p_s[g * PP + kc * 8 + tg + 4]);
                uint32_t a3 = __float_as_uint(p_s[(g + 8) * PP + kc * 8 + tg + 4]);
                #pragma unroll
                for (int c2 = 0; c2 < 4; c2++) {
                    uint32_t b0 = cvt_tf32(kvs[(kc * 8 + tg) * KP + nb + c2 * 8 + g]);
                    uint32_t b1 = cvt_tf32(kvs[(kc * 8 + tg + 4) * KP + nb + c2 * 8 + g]);
                    mma_tf32(acc[c2], a0, a1, a2, a3, b0, b1);
                }
            }
        }
        __syncthreads();   // protect kvs(buf) before tile+2 prefetch
    }

    if (lane == 0) l_s[wid] = l_cur;
    __syncthreads();

    // epilogue: normalize + store
    {
        int nb = wid * 32;
        float ig = 1.f / l_s[g], ig8 = 1.f / l_s[g + 8];
        #pragma unroll
        for (int c2 = 0; c2 < 4; c2++) {
            int d = nb + c2 * 8 + 2 * tg;
            float2 v0 = { acc[c2][0] * ig,  acc[c2][1] * ig  };
            float2 v1 = { acc[c2][2] * ig8, acc[c2][3] * ig8 };
            *(float2*)&g_attn[(q * 16 + g) * 512 + d]       = v0;
            *(float2*)&g_attn[(q * 16 + g + 8) * 512 + d]   = v1;
        }
    }
}

// ------------------ launcher ------------------
extern "C" void kernel_launch(void* const* d_in, const int* in_sizes, int n_in,
                              void* d_out, int out_size)
{
    const float* q_latent = (const float*)d_in[0];
    const float* hs       = (const float*)d_in[1];
    const float* cosb     = (const float*)d_in[2];
    const float* sinb     = (const float*)d_in[3];
    const float* q_pass   = (const float*)d_in[4];
    const float* q_rot    = (const float*)d_in[5];
    const float* k_pass   = (const float*)d_in[6];
    const float* k_rot    = (const float*)d_in[7];
    const float* kv_b     = (const float*)d_in[9];
    const float* wq_b     = (const float*)d_in[10];
    const float* wk       = (const float*)d_in[11];
    const float* k_norm   = (const float*)d_in[12];
    const float* wproj    = (const float*)d_in[13];
    const float* wproj_b  = (const float*)d_in[14];
    float* out = (float*)d_out;

    float *ql, *ckv, *wtmp, *qbuf, *attn;
    cudaGetSymbolAddress((void**)&ql,   g_ql);
    cudaGetSymbolAddress((void**)&ckv,  g_ckv);
    cudaGetSymbolAddress((void**)&wtmp, g_wtmp);
    cudaGetSymbolAddress((void**)&qbuf, g_q);
    cudaGetSymbolAddress((void**)&attn, g_attn);

    sgemm_k<<<dim3(32, 32, 1), 256>>>(q_latent, wq_b, ql,
        2048, 2048, 1536, 1536, 1536, 2048, 0, 0, 0, 1);
    sgemm_k<<<dim3(2, 32, 1), 256>>>(hs, wk, ckv,
        2048, 128, 2048, 2048, 2048, 128, 0, 0, 0, 1);
    sgemm_k<<<dim3(1, 32, 1), 256>>>(hs, wproj, wtmp,
        2048, 16, 2048, 2048, 2048, 16, 0, 0, 0, 1);
    prep_k<<<2048, 128>>>(cosb, sinb, k_pass, k_rot, q_rot, k_norm, wproj_b);
    sgemm_k<<<dim3(8, 32, 16), 256>>>(q_pass, kv_b, qbuf,
        2048, 512, 128, 128, 512, 9216,
        2048LL * 128, 256LL * 512, 576, 0);
    score_k<<<dim3(32, 16), 256>>>();
    topk_k<<<1024, 1024>>>();
    cudaFuncSetAttribute(attn_k, cudaFuncAttributeMaxDynamicSharedMemorySize, ATTN_SMEM);
    attn_k<<<2048, 512, ATTN_SMEM>>>();
    sgemm_k<<<dim3(2, 32, 16), 256>>>(attn, kv_b + 128 * 512, out,
        2048, 128, 512, 8192, 512, 2048,
        512, 256LL * 512, 128, 1);
}

// round 6
// speedup vs baseline: 4.5992x; 1.0279x over previous
#include <cuda_runtime.h>
#include <stdint.h>
#include <math.h>

#define SQ       2048
#define NH       16
#define DQK      576
#define KVL      512
#define NTOP     1024
#define SCALINGF 0.08838834764831845f  // 128^-0.5

// ------------------ device scratch (no allocation) ------------------
__device__ float g_ql  [SQ * 2048];
__device__ float g_ckv [SQ * 128];
__device__ float g_wtmp[SQ * NH];
__device__ float g_iq  [SQ * NH * 128];
__device__ float g_ik  [SQ * 128];
__device__ float g_w   [SQ * NH];
__device__ float g_q   [SQ * NH * DQK];
__device__ float g_kv  [SQ * DQK];
__device__ float g_score[SQ * SQ];
__device__ int   g_topk [SQ * NTOP];
__device__ float g_attn [SQ * NH * KVL];

// ------------------ cp.async helpers ------------------
__device__ __forceinline__ void cp16(void* dst, const void* src) {
    unsigned s = (unsigned)__cvta_generic_to_shared(dst);
    asm volatile("cp.async.cg.shared.global [%0], [%1], 16;\n" :: "r"(s), "l"(src));
}
__device__ __forceinline__ void cp_commit() {
    asm volatile("cp.async.commit_group;\n" ::: "memory");
}
__device__ __forceinline__ void cp_wait1() {
    asm volatile("cp.async.wait_group 1;\n" ::: "memory");
}

// ------------------ tf32 mma helpers ------------------
__device__ __forceinline__ uint32_t cvt_tf32(float x) {
    uint32_t r; asm("cvt.rna.tf32.f32 %0, %1;" : "=r"(r) : "f"(x)); return r;
}
__device__ __forceinline__ void mma_tf32(float* c,
    uint32_t a0, uint32_t a1, uint32_t a2, uint32_t a3,
    uint32_t b0, uint32_t b1)
{
    asm volatile(
        "mma.sync.aligned.m16n8k8.row.col.f32.tf32.tf32.f32 "
        "{%0,%1,%2,%3}, {%4,%5,%6,%7}, {%8,%9}, {%0,%1,%2,%3};\n"
        : "+f"(c[0]), "+f"(c[1]), "+f"(c[2]), "+f"(c[3])
        : "r"(a0), "r"(a1), "r"(a2), "r"(a3), "r"(b0), "r"(b1));
}

// ------------------ tensor-core GEMM, optional 3xTF32: C = A @ op(B) ------------------
// A: M x K (row, lda).  transB=1: B is N x K (row, ldb).  transB=0: B is K x N (row, ldb).
// Requires M,N % 64 == 0 and K % 32 == 0 (true for all call sites).
__global__ __launch_bounds__(256) void tgemm_k(
    const float* __restrict__ A, const float* __restrict__ B, float* __restrict__ C,
    int M, int N, int K, int lda, int ldb, int ldc,
    long long sA, long long sB, long long sC, int transB, int triple)
{
    A += (long long)blockIdx.z * sA;
    B += (long long)blockIdx.z * sB;
    C += (long long)blockIdx.z * sC;
    __shared__ float As[64 * 33], Ae[64 * 33], Bs[64 * 33], Be[64 * 33];
    int tid = threadIdx.x, lane = tid & 31, warp = tid >> 5;
    int wm = (warp & 3) * 16, wn = (warp >> 2) * 32;
    int g = lane >> 2, tg = lane & 3;
    int m0 = blockIdx.y * 64, n0 = blockIdx.x * 64;
    float acc[4][4] = {};

    for (int k0 = 0; k0 < K; k0 += 32) {
        for (int e = tid; e < 2048; e += 256) {
            int m = e >> 5, k = e & 31;
            float v = A[(long long)(m0 + m) * lda + k0 + k];
            float t = __uint_as_float(cvt_tf32(v));
            As[m * 33 + k] = t;
            if (triple) Ae[m * 33 + k] = __uint_as_float(cvt_tf32(v - t));
        }
        if (transB) {
            for (int e = tid; e < 2048; e += 256) {
                int n = e >> 5, k = e & 31;
                float v = B[(long long)(n0 + n) * ldb + k0 + k];
                float t = __uint_as_float(cvt_tf32(v));
                Bs[n * 33 + k] = t;
                if (triple) Be[n * 33 + k] = __uint_as_float(cvt_tf32(v - t));
            }
        } else {
            for (int e = tid; e < 2048; e += 256) {
                int n = e & 63, k = e >> 6;
                float v = B[(long long)(k0 + k) * ldb + n0 + n];
                float t = __uint_as_float(cvt_tf32(v));
                Bs[n * 33 + k] = t;
                if (triple) Be[n * 33 + k] = __uint_as_float(cvt_tf32(v - t));
            }
        }
        __syncthreads();
        #pragma unroll
        for (int kc = 0; kc < 4; kc++) {
            int kb = kc * 8;
            uint32_t a0 = __float_as_uint(As[(wm + g) * 33 + kb + tg]);
            uint32_t a1 = __float_as_uint(As[(wm + g + 8) * 33 + kb + tg]);
            uint32_t a2 = __float_as_uint(As[(wm + g) * 33 + kb + tg + 4]);
            uint32_t a3 = __float_as_uint(As[(wm + g + 8) * 33 + kb + tg + 4]);
            if (!triple) {
                #pragma unroll
                for (int nc = 0; nc < 4; nc++) {
                    uint32_t b0 = __float_as_uint(Bs[(wn + nc * 8 + g) * 33 + kb + tg]);
                    uint32_t b1 = __float_as_uint(Bs[(wn + nc * 8 + g) * 33 + kb + tg + 4]);
                    mma_tf32(acc[nc], a0, a1, a2, a3, b0, b1);
                }
            } else {
                uint32_t r0 = __float_as_uint(Ae[(wm + g) * 33 + kb + tg]);
                uint32_t r1 = __float_as_uint(Ae[(wm + g + 8) * 33 + kb + tg]);
                uint32_t r2 = __float_as_uint(Ae[(wm + g) * 33 + kb + tg + 4]);
                uint32_t r3 = __float_as_uint(Ae[(wm + g + 8) * 33 + kb + tg + 4]);
                #pragma unroll
                for (int nc = 0; nc < 4; nc++) {
                    uint32_t b0 = __float_as_uint(Bs[(wn + nc * 8 + g) * 33 + kb + tg]);
                    uint32_t b1 = __float_as_uint(Bs[(wn + nc * 8 + g) * 33 + kb + tg + 4]);
                    uint32_t e0 = __float_as_uint(Be[(wn + nc * 8 + g) * 33 + kb + tg]);
                    uint32_t e1 = __float_as_uint(Be[(wn + nc * 8 + g) * 33 + kb + tg + 4]);
                    mma_tf32(acc[nc], r0, r1, r2, r3, b0, b1);
                    mma_tf32(acc[nc], a0, a1, a2, a3, e0, e1);
                    mma_tf32(acc[nc], a0, a1, a2, a3, b0, b1);
                }
            }
        }
        __syncthreads();
    }
    #pragma unroll
    for (int nc = 0; nc < 4; nc++) {
        int col = n0 + wn + nc * 8 + 2 * tg;
        float2 v0 = { acc[nc][0], acc[nc][1] };
        float2 v1 = { acc[nc][2], acc[nc][3] };
        *(float2*)&C[(long long)(m0 + wm + g) * ldc + col]     = v0;
        *(float2*)&C[(long long)(m0 + wm + g + 8) * ldc + col] = v1;
    }
}

// ------------------ generic batched SGEMM (exact fp32, small GEMMs) ------------------
__global__ __launch_bounds__(256) void sgemm_k(
    const float* __restrict__ A, const float* __restrict__ B, float* __restrict__ C,
    int M, int N, int K, int lda, int ldb, int ldc,
    long long sA, long long sB, long long sC, int transB)
{
    A += (long long)blockIdx.z * sA;
    B += (long long)blockIdx.z * sB;
    C += (long long)blockIdx.z * sC;
    __shared__ float As[16][65];
    __shared__ float Bs[16][65];
    int tid = threadIdx.x, tx = tid & 15, ty = tid >> 4;
    int m0 = blockIdx.y * 64, n0 = blockIdx.x * 64;
    float acc[4][4] = {};
    for (int k0 = 0; k0 < K; k0 += 16) {
        for (int e = tid; e < 1024; e += 256) {
            int m = e >> 4, k = e & 15;
            int gm = m0 + m, gk = k0 + k;
            As[k][m] = (gm < M && gk < K) ? A[(long long)gm * lda + gk] : 0.f;
        }
        if (transB) {
            for (int e = tid; e < 1024; e += 256) {
                int n = e >> 4, k = e & 15;
                int gn = n0 + n, gk = k0 + k;
                Bs[k][n] = (gn < N && gk < K) ? B[(long long)gn * ldb + gk] : 0.f;
            }
        } else {
            for (int e = tid; e < 1024; e += 256) {
                int k = e >> 6, n = e & 63;
                int gn = n0 + n, gk = k0 + k;
                Bs[k][n] = (gn < N && gk < K) ? B[(long long)gk * ldb + gn] : 0.f;
            }
        }
        __syncthreads();
        #pragma unroll
        for (int kk = 0; kk < 16; kk++) {
            float a[4], b[4];
            #pragma unroll
            for (int i = 0; i < 4; i++) a[i] = As[kk][ty * 4 + i];
            #pragma unroll
            for (int j = 0; j < 4; j++) b[j] = Bs[kk][tx * 4 + j];
            #pragma unroll
            for (int i = 0; i < 4; i++)
                #pragma unroll
                for (int j = 0; j < 4; j++) acc[i][j] += a[i] * b[j];
        }
        __syncthreads();
    }
    #pragma unroll
    for (int i = 0; i < 4; i++) {
        int gm = m0 + ty * 4 + i;
        if (gm >= M) continue;
        #pragma unroll
        for (int j = 0; j < 4; j++) {
            int gn = n0 + tx * 4 + j;
            if (gn >= N) continue;
            C[(long long)gm * ldc + gn] = acc[i][j];
        }
    }
}

// ------------------ prep: rope / rmsnorm / concats ------------------
__global__ __launch_bounds__(128) void prep_k(
    const float* __restrict__ cosb, const float* __restrict__ sinb,
    const float* __restrict__ k_pass, const float* __restrict__ k_rot,
    const float* __restrict__ q_rot, const float* __restrict__ k_norm_w,
    const float* __restrict__ wproj_b)
{
    int s = blockIdx.x, t = threadIdx.x;
    const float* cs = cosb + s * 64;
    const float* sn = sinb + s * 64;
    if (t < 32) {
        float x0 = g_ckv[s * 128 + 2 * t], x1 = g_ckv[s * 128 + 2 * t + 1];
        g_ik[s * 128 + t]      = x0 * cs[t]      - x1 * sn[t];
        g_ik[s * 128 + 32 + t] = x1 * cs[32 + t] + x0 * sn[32 + t];
    }
    __shared__ float partials[4];
    float v = 0.f;
    if (t < 64) { float x = g_ckv[s * 128 + 64 + t]; v = x * x; }
    for (int o = 16; o > 0; o >>= 1) v += __shfl_xor_sync(0xffffffffu, v, o);
    if ((t & 31) == 0) partials[t >> 5] = v;
    __syncthreads();
    float var = (partials[0] + partials[1]) * (1.f / 64.f);
    float inv = rsqrtf(var + 1e-6f);
    if (t < 64)
        g_ik[s * 128 + 64 + t] = g_ckv[s * 128 + 64 + t] * inv * k_norm_w[t];
    for (int u = t; u < 16 * 32; u += 128) {
        int h = u >> 5, i = u & 31;
        float x0 = g_ql[s * 2048 + h * 128 + 2 * i];
        float x1 = g_ql[s * 2048 + h * 128 + 2 * i + 1];
        g_iq[(s * 16 + h) * 128 + i]      = x0 * cs[i]      - x1 * sn[i];
        g_iq[(s * 16 + h) * 128 + 32 + i] = x1 * cs[32 + i] + x0 * sn[32 + i];
    }
    for (int u = t; u < 16 * 64; u += 128) {
        int h = u >> 6, i = u & 63;
        g_iq[(s * 16 + h) * 128 + 64 + i] = g_ql[s * 2048 + h * 128 + 64 + i];
    }
    if (t < 16) g_w[s * 16 + t] = fabsf(g_wtmp[s * 16 + t] + wproj_b[t]);
    for (int u = t; u < 512; u += 128) g_kv[s * 576 + u] = k_pass[s * 512 + u];
    if (t < 64) g_kv[s * 576 + 512 + t] = k_rot[s * 64 + t];
    for (int u = t; u < 16 * 64; u += 128) {
        int h = u >> 6, j = u & 63;
        g_q[(s * 16 + h) * 576 + 512 + j] = q_rot[(h * 2048 + s) * 64 + j];
    }
}

// ------------------ indexer scores for rows q >= 1024 (fp32, exact) ------------------
__global__ __launch_bounds__(256) void score_k()
{
    __shared__ float Qs[32][65];
    __shared__ float Ks[32][65];
    __shared__ float ws[64];
    int q0 = 1024 + blockIdx.y * 64;
    int k0 = blockIdx.x * 64;
    if (k0 > q0 + 63) return;
    int tid = threadIdx.x, tx = tid & 15, ty = tid >> 4;
    float acc[4][4] = {};
    for (int h = 0; h < 16; h++) {
        float dacc[4][4] = {};
        for (int d0 = 0; d0 < 128; d0 += 32) {
            __syncthreads();
            for (int e = tid; e < 2048; e += 256) {
                int m = e >> 5, dd = e & 31;
                Qs[dd][m] = g_iq[((q0 + m) * 16 + h) * 128 + d0 + dd];
                Ks[dd][m] = g_ik[(k0 + m) * 128 + d0 + dd];
            }
            __syncthreads();
            #pragma unroll
            for (int dd = 0; dd < 32; dd++) {
                float a[4], b[4];
                #pragma unroll
                for (int i = 0; i < 4; i++) a[i] = Qs[dd][ty * 4 + i];
                #pragma unroll
                for (int j = 0; j < 4; j++) b[j] = Ks[dd][tx * 4 + j];
                #pragma unroll
                for (int i = 0; i < 4; i++)
                    #pragma unroll
                    for (int j = 0; j < 4; j++) dacc[i][j] += a[i] * b[j];
            }
        }
        __syncthreads();
        if (tid < 64) ws[tid] = g_w[(q0 + tid) * 16 + h];
        __syncthreads();
        #pragma unroll
        for (int i = 0; i < 4; i++)
            #pragma unroll
            for (int j = 0; j < 4; j++)
                acc[i][j] += ws[ty * 4 + i] * fmaxf(dacc[i][j] * SCALINGF, 0.f);
    }
    #pragma unroll
    for (int i = 0; i < 4; i++)
        #pragma unroll
        for (int j = 0; j < 4; j++)
            g_score[(q0 + ty * 4 + i) * 2048 + k0 + tx * 4 + j] = acc[i][j];
}

// ------------------ top-1024 per row (bitonic, jax tie-break) ------------------
__global__ __launch_bounds__(1024) void topk_k()
{
    __shared__ unsigned long long key[2048];
    int q = 1024 + blockIdx.x;
    int t = threadIdx.x;
    for (int u = t; u < 2048; u += 1024) {
        unsigned long long kk = 0ull;
        if (u <= q) {
            unsigned int b = __float_as_uint(g_score[q * 2048 + u]);  // score >= 0
            kk = ((unsigned long long)b << 32) | (unsigned int)(~u);
        }
        key[u] = kk;
    }
    __syncthreads();
    for (int ks = 2; ks <= 2048; ks <<= 1) {
        for (int j = ks >> 1; j > 0; j >>= 1) {
            int i = ((t & ~(j - 1)) << 1) | (t & (j - 1));
            int p = i | j;
            bool desc = (i & ks) == 0;
            unsigned long long a = key[i], b = key[p];
            if ((a < b) == desc) { key[i] = b; key[p] = a; }
            __syncthreads();
        }
    }
    g_topk[q * 1024 + t] = (int)(~(unsigned int)(key[t] & 0xFFFFFFFFull));
}

// ------------------ single-pass flash attention, tf32 tensor cores ------------------
#define KP 580                 // kv smem pitch (floats)
#define QP 580                 // q smem pitch
#define PP 36                  // p smem pitch
#define KVBUF (32 * KP)        // 18560 floats per buffer
#define ATTN_SMEM ((16*QP + 2*KVBUF + 4*16*33 + 16*PP + 32) * 4)

__global__ __launch_bounds__(512) void attn_k()
{
    extern __shared__ float sm[];
    float* qsm  = sm;                       // 16*580
    float* kvb  = qsm + 16 * QP;            // 2*18560
    float* part = kvb + 2 * KVBUF;          // 4*16*33 = 2112
    float* p_s  = part + 2112;              // 16*36
    float* f_s  = p_s + 16 * PP;            // 16
    float* l_s  = f_s + 16;                 // 16

    int q = blockIdx.x, t = threadIdx.x;
    int L = (q < 1024) ? (q + 1) : 1024;
    const int* sel = (q < 1024) ? (const int*)0 : &g_topk[q * 1024];
    int nt = (L + 31) >> 5;

    int wid = t >> 5, lane = t & 31;
    int g = lane >> 2, tg = lane & 3;
    int gj = t >> 4, gf = t & 15;

    {
        const float4* qg = (const float4*)&g_q[q * 16 * 576];
        for (int i = t; i < 2304; i += 512) {
            int row = i / 144, f4 = i % 144;
            float4 v = qg[i];
            float* d = qsm + row * QP + f4 * 4;
            d[0] = __uint_as_float(cvt_tf32(v.x));
            d[1] = __uint_as_float(cvt_tf32(v.y));
            d[2] = __uint_as_float(cvt_tf32(v.z));
            d[3] = __uint_as_float(cvt_tf32(v.w));
        }
    }

    float acc[4][4] = {};
    float m_cur = -1e30f, l_cur = 0.f;

    {
        float* dst = kvb + gj * KP;
        if (gj < L) {
            int keyi = sel ? sel[gj] : gj;
            const float* src = &g_kv[keyi * 576];
            #pragma unroll
            for (int i = 0; i < 9; i++) {
                int f4 = gf + 16 * i;
                cp16(dst + f4 * 4, src + f4 * 4);
            }
        } else {
            float4 z = {0, 0, 0, 0};
            #pragma unroll
            for (int i = 0; i < 9; i++)
                *(float4*)(dst + (gf + 16 * i) * 4) = z;
        }
    }
    cp_commit();
    __syncthreads();

    int nc = wid & 3;
    int kq = wid >> 2;

    for (int tile = 0; tile < nt; tile++) {
        int buf = tile & 1;
        float* kvs = kvb + buf * KVBUF;
        if (tile + 1 < nt) {
            int jj = (tile + 1) * 32 + gj;
            float* dst = kvb + (buf ^ 1) * KVBUF + gj * KP;
            if (jj < L) {
                int keyi = sel ? sel[jj] : jj;
                const float* src = &g_kv[keyi * 576];
                #pragma unroll
                for (int i = 0; i < 9; i++) {
                    int f4 = gf + 16 * i;
                    cp16(dst + f4 * 4, src + f4 * 4);
                }
            } else {
                float4 z = {0, 0, 0, 0};
                #pragma unroll
                for (int i = 0; i < 9; i++)
                    *(float4*)(dst + (gf + 16 * i) * 4) = z;
            }
        }
        cp_commit();
        cp_wait1();
        __syncthreads();

        {
            float c[4] = {0, 0, 0, 0};
            #pragma unroll
            for (int kc = 0; kc < 18; kc++) {
                int k0 = kq * 144 + kc * 8;
                uint32_t a0 = __float_as_uint(qsm[g * QP + k0 + tg]);
                uint32_t a1 = __float_as_uint(qsm[(g + 8) * QP + k0 + tg]);
                uint32_t a2 = __float_as_uint(qsm[g * QP + k0 + tg + 4]);
                uint32_t a3 = __float_as_uint(qsm[(g + 8) * QP + k0 + tg + 4]);
                uint32_t b0 = cvt_tf32(kvs[(nc * 8 + g) * KP + k0 + tg]);
                uint32_t b1 = cvt_tf32(kvs[(nc * 8 + g) * KP + k0 + tg + 4]);
                mma_tf32(c, a0, a1, a2, a3, b0, b1);
            }
            float* pp = part + kq * 528;
            pp[g * 33 + nc * 8 + 2 * tg]           = c[0];
            pp[g * 33 + nc * 8 + 2 * tg + 1]       = c[1];
            pp[(g + 8) * 33 + nc * 8 + 2 * tg]     = c[2];
            pp[(g + 8) * 33 + nc * 8 + 2 * tg + 1] = c[3];
        }
        __syncthreads();

        {
            float val = part[wid * 33 + lane] + part[528 + wid * 33 + lane]
                      + part[1056 + wid * 33 + lane] + part[1584 + wid * 33 + lane];
            val *= SCALINGF;
            int jj = tile * 32 + lane;
            val = (jj < L) ? val : -1e30f;
            float mx = val;
            #pragma unroll
            for (int o = 16; o > 0; o >>= 1)
                mx = fmaxf(mx, __shfl_xor_sync(0xffffffffu, mx, o));
            float m_new = fmaxf(m_cur, mx);
            float factor = __expf(m_cur - m_new);
            float p = __uint_as_float(cvt_tf32(__expf(val - m_new)));
            float ps = p;
            #pragma unroll
            for (int o = 16; o > 0; o >>= 1)
                ps += __shfl_xor_sync(0xffffffffu, ps, o);
            l_cur = l_cur * factor + ps;
            m_cur = m_new;
            p_s[wid * PP + lane] = p;
            if (lane == 0) f_s[wid] = factor;
        }
        __syncthreads();

        {
            int nb = wid * 32;
            float fg = f_s[g], fg8 = f_s[g + 8];
            #pragma unroll
            for (int c2 = 0; c2 < 4; c2++) {
                acc[c2][0] *= fg;  acc[c2][1] *= fg;
                acc[c2][2] *= fg8; acc[c2][3] *= fg8;
            }
            #pragma unroll
            for (int kc = 0; kc < 4; kc++) {
                uint32_t a0 = __float_as_uint(p_s[g * PP + kc * 8 + tg]);
                uint32_t a1 = __float_as_uint(p_s[(g + 8) * PP + kc * 8 + tg]);
                uint32_t a2 = __float_as_uint(p_s[g * PP + kc * 8 + tg + 4]);
                uint32_t a3 = __float_as_uint(p_s[(g + 8) * PP + kc * 8 + tg + 4]);
                #pragma unroll
                for (int c2 = 0; c2 < 4; c2++) {
                    uint32_t b0 = cvt_tf32(kvs[(kc * 8 + tg) * KP + nb + c2 * 8 + g]);
                    uint32_t b1 = cvt_tf32(kvs[(kc * 8 + tg + 4) * KP + nb + c2 * 8 + g]);
                    mma_tf32(acc[c2], a0, a1, a2, a3, b0, b1);
                }
            }
        }
        __syncthreads();
    }

    if (lane == 0) l_s[wid] = l_cur;
    __syncthreads();

    {
        int nb = wid * 32;
        float ig = 1.f / l_s[g], ig8 = 1.f / l_s[g + 8];
        #pragma unroll
        for (int c2 = 0; c2 < 4; c2++) {
            int d = nb + c2 * 8 + 2 * tg;
            float2 v0 = { acc[c2][0] * ig,  acc[c2][1] * ig  };
            float2 v1 = { acc[c2][2] * ig8, acc[c2][3] * ig8 };
            *(float2*)&g_attn[(q * 16 + g) * 512 + d]       = v0;
            *(float2*)&g_attn[(q * 16 + g + 8) * 512 + d]   = v1;
        }
    }
}

// ------------------ launcher ------------------
extern "C" void kernel_launch(void* const* d_in, const int* in_sizes, int n_in,
                              void* d_out, int out_size)
{
    const float* q_latent = (const float*)d_in[0];
    const float* hs       = (const float*)d_in[1];
    const float* cosb     = (const float*)d_in[2];
    const float* sinb     = (const float*)d_in[3];
    const float* q_pass   = (const float*)d_in[4];
    const float* q_rot    = (const float*)d_in[5];
    const float* k_pass   = (const float*)d_in[6];
    const float* k_rot    = (const float*)d_in[7];
    const float* kv_b     = (const float*)d_in[9];
    const float* wq_b     = (const float*)d_in[10];
    const float* wk       = (const float*)d_in[11];
    const float* k_norm   = (const float*)d_in[12];
    const float* wproj    = (const float*)d_in[13];
    const float* wproj_b  = (const float*)d_in[14];
    float* out = (float*)d_out;

    float *ql, *ckv, *wtmp, *qbuf, *attn;
    cudaGetSymbolAddress((void**)&ql,   g_ql);
    cudaGetSymbolAddress((void**)&ckv,  g_ckv);
    cudaGetSymbolAddress((void**)&wtmp, g_wtmp);
    cudaGetSymbolAddress((void**)&qbuf, g_q);
    cudaGetSymbolAddress((void**)&attn, g_attn);

    // ql = q_latent @ wq_b^T (selection-critical -> 3xTF32)
    tgemm_k<<<dim3(32, 32, 1), 256>>>(q_latent, wq_b, ql,
        2048, 2048, 1536, 1536, 1536, 2048, 0, 0, 0, 1, 1);
    // ckv = hs @ wk^T (selection-critical, small -> exact fp32)
    sgemm_k<<<dim3(2, 32, 1), 256>>>(hs, wk, ckv,
        2048, 128, 2048, 2048, 2048, 128, 0, 0, 0, 1);
    // wtmp = hs @ wproj^T (selection-critical, tiny -> exact fp32)
    sgemm_k<<<dim3(1, 32, 1), 256>>>(hs, wproj, wtmp,
        2048, 16, 2048, 2048, 2048, 16, 0, 0, 0, 1);
    prep_k<<<2048, 128>>>(cosb, sinb, k_pass, k_rot, q_rot, k_norm, wproj_b);
    // q_abs[h] = q_pass[h] @ k_b[h]  (3xTF32, batched over 16 heads)
    tgemm_k<<<dim3(8, 32, 16), 256>>>(q_pass, kv_b, qbuf,
        2048, 512, 128, 128, 512, 9216,
        2048LL * 128, 256LL * 512, 576, 0, 1);
    score_k<<<dim3(32, 16), 256>>>();
    topk_k<<<1024, 1024>>>();
    cudaFuncSetAttribute(attn_k, cudaFuncAttributeMaxDynamicSharedMemorySize, ATTN_SMEM);
    attn_k<<<2048, 512, ATTN_SMEM>>>();
    // out[s][h][d] = attn[s][h][:] . v_b[h][d][:]  (3xTF32, batched over 16 heads)
    tgemm_k<<<dim3(2, 32, 16), 256>>>(attn, kv_b + 128 * 512, out,
        2048, 128, 512, 8192, 512, 2048,
        512, 256LL * 512, 128, 1, 1);
}